// round 13
// baseline (speedup 1.0000x reference)
#include <cuda_runtime.h>
#include <cuda_bf16.h>
#include <math.h>
#include <stdint.h>

// ---------------- Problem constants ----------------
#define BB 4
#define LL 2048
#define DMODEL 1024
#define DINNER 2048
#define DSTATE 32
#define DTRANK 64
#define MM (BB*LL)          // 8192 rows
#define XPROJ_N 128

// ---------------- Scratch ----------------
__device__ float g_xn [MM*DMODEL];
__device__ float g_xz [MM*(2*DINNER)];
__device__ float g_uc [MM*DINNER];
__device__ float g_dbl[MM*XPROJ_N];
__device__ float g_dt [MM*DINNER];
__device__ float g_y  [MM*DINNER];

// ---------------- helpers ----------------
__device__ __forceinline__ uint32_t smem_u32(const void* p){
    uint32_t a;
    asm("{ .reg .u64 t; cvta.to.shared.u64 t, %1; cvt.u32.u64 %0, t; }" : "=r"(a) : "l"(p));
    return a;
}
__device__ __forceinline__ void mma_tf32(float* c, const uint32_t* a, const uint32_t* b){
    asm volatile(
        "mma.sync.aligned.m16n8k8.row.col.f32.tf32.tf32.f32 "
        "{%0,%1,%2,%3}, {%4,%5,%6,%7}, {%8,%9}, {%0,%1,%2,%3};"
        : "+f"(c[0]), "+f"(c[1]), "+f"(c[2]), "+f"(c[3])
        : "r"(a[0]), "r"(a[1]), "r"(a[2]), "r"(a[3]), "r"(b[0]), "r"(b[1]));
}
__device__ __forceinline__ void ldsm4(uint32_t* r, uint32_t addr){
    asm volatile("ldmatrix.sync.aligned.m8n8.x4.shared.b16 {%0,%1,%2,%3}, [%4];"
        : "=r"(r[0]), "=r"(r[1]), "=r"(r[2]), "=r"(r[3]) : "r"(addr));
}

// ---------------- tf32 mma.sync GEMM, 512 threads (16 warps 4m x 4n) ----------
// C[m,n] = sum_k A[m,k]*Bw[n,k]; A row-major lda, Bw row-major [N,K].
// BM=64*MTW (128 or 64), BN=128, BK=32. Warp tile (16*MTW) x 32. 2-stage cp.async.
// EPI: 0 none, 1 softplus(acc+bias[n]), 2 acc+resid.
#define GP 36                      // smem row pitch in floats
#define TILE_ROW_BYTES (GP*4)      // 144

template<int MTW, int EPI>
__global__ __launch_bounds__(512, 2) void mma_gemm(
    const float* __restrict__ A, int lda,
    const float* __restrict__ Bw,
    float* __restrict__ C,
    int N, int K,
    const float* __restrict__ bias,
    const float* __restrict__ resid)
{
    constexpr int BM  = 64*MTW;
    constexpr int SAB = BM * TILE_ROW_BYTES;        // A stage bytes
    constexpr int SBB = 128 * TILE_ROW_BYTES;       // B stage bytes
    constexpr int STG = SAB + SBB;                  // one stage (A then B)

    extern __shared__ char dynsmem[];
    const uint32_t sm32 = smem_u32(dynsmem);

    const int tid  = threadIdx.x;
    const int wid  = tid >> 5, lane = tid & 31;
    const int g    = lane >> 2;
    const int c2   = (lane & 3) * 2;
    const int wm   = (wid >> 2) * (16*MTW);   // 4 warp rows
    const int wn   = (wid & 3) * 32;          // 4 warp cols
    const int m0   = blockIdx.y * BM;
    const int n0   = blockIdx.x * 128;

    // gmem->smem: 512 threads, row = tid/8 (0..63) + 64*i, 16B chunk = tid%8
    const int lrow = tid >> 3;
    const int lk16 = (tid & 7) * 16;

    const float* Ap0 = A  + (size_t)(m0 + lrow) * lda + (lk16 >> 2);
    const float* Bp0 = Bw + (size_t)(n0 + lrow) * K   + (lk16 >> 2);

    const uint32_t aoff = ((wm + (lane & 15))*GP + (lane >> 4)*4) * 4;
    const uint32_t boff = ((wn + 8*(lane >> 4) + (lane & 7))*GP + ((lane >> 3) & 1)*4) * 4;

    float acc[MTW][4][4];
    #pragma unroll
    for (int i = 0; i < MTW; ++i)
        #pragma unroll
        for (int j = 0; j < 4; ++j)
            #pragma unroll
            for (int q = 0; q < 4; ++q) acc[i][j][q] = 0.f;

    const int KT = K / 32;

    // prologue: tile 0 -> stage 0
    {
        #pragma unroll
        for (int i = 0; i < BM/64; ++i)
            asm volatile("cp.async.cg.shared.global [%0], [%1], 16;"
                :: "r"(sm32 + (lrow + 64*i)*TILE_ROW_BYTES + lk16),
                   "l"(Ap0 + (size_t)(64*i)*lda));
        #pragma unroll
        for (int i = 0; i < 2; ++i)
            asm volatile("cp.async.cg.shared.global [%0], [%1], 16;"
                :: "r"(sm32 + SAB + (lrow + 64*i)*TILE_ROW_BYTES + lk16),
                   "l"(Bp0 + (size_t)(64*i)*K));
        asm volatile("cp.async.commit_group;" ::: "memory");
    }

    for (int kt = 0; kt < KT; ++kt) {
        const int s = kt & 1;
        if (kt + 1 < KT) {
            const uint32_t da = sm32 + (1 - s)*STG;
            const float* Apn = Ap0 + (kt + 1)*32;
            const float* Bpn = Bp0 + (kt + 1)*32;
            #pragma unroll
            for (int i = 0; i < BM/64; ++i)
                asm volatile("cp.async.cg.shared.global [%0], [%1], 16;"
                    :: "r"(da + (lrow + 64*i)*TILE_ROW_BYTES + lk16),
                       "l"(Apn + (size_t)(64*i)*lda));
            #pragma unroll
            for (int i = 0; i < 2; ++i)
                asm volatile("cp.async.cg.shared.global [%0], [%1], 16;"
                    :: "r"(da + SAB + (lrow + 64*i)*TILE_ROW_BYTES + lk16),
                       "l"(Bpn + (size_t)(64*i)*K));
            asm volatile("cp.async.commit_group;" ::: "memory");
            asm volatile("cp.async.wait_group 1;" ::: "memory");
        } else {
            asm volatile("cp.async.wait_group 0;" ::: "memory");
        }
        __syncthreads();

        const uint32_t sA = sm32 + s*STG;
        const uint32_t sB = sA + SAB;
        #pragma unroll
        for (int k8 = 0; k8 < 4; ++k8) {
            const uint32_t kbyte = k8 * 32;
            uint32_t afr[MTW][4];
            #pragma unroll
            for (int mt = 0; mt < MTW; ++mt)
                ldsm4(afr[mt], sA + aoff + mt*(16*TILE_ROW_BYTES) + kbyte);
            uint32_t bfr[4][2];
            {
                uint32_t t0[4], t1[4];
                ldsm4(t0, sB + boff + kbyte);
                ldsm4(t1, sB + boff + 16*TILE_ROW_BYTES + kbyte);
                bfr[0][0]=t0[0]; bfr[0][1]=t0[1]; bfr[1][0]=t0[2]; bfr[1][1]=t0[3];
                bfr[2][0]=t1[0]; bfr[2][1]=t1[1]; bfr[3][0]=t1[2]; bfr[3][1]=t1[3];
            }
            #pragma unroll
            for (int mt = 0; mt < MTW; ++mt)
                #pragma unroll
                for (int nt = 0; nt < 4; ++nt)
                    mma_tf32(acc[mt][nt], afr[mt], bfr[nt]);
        }
        __syncthreads();
    }

    // epilogue
    #pragma unroll
    for (int mt = 0; mt < MTW; ++mt) {
        #pragma unroll
        for (int nt = 0; nt < 4; ++nt) {
            const int m = m0 + wm + mt*16 + g;
            const int n = n0 + wn + nt*8 + c2;
            float v0 = acc[mt][nt][0], v1 = acc[mt][nt][1];
            float v2 = acc[mt][nt][2], v3 = acc[mt][nt][3];
            if (EPI == 1) {
                float b0 = bias[n], b1 = bias[n+1];
                float t0 = v0 + b0; v0 = (t0 > 20.f) ? t0 : __logf(1.f + __expf(t0));
                float t1 = v1 + b1; v1 = (t1 > 20.f) ? t1 : __logf(1.f + __expf(t1));
                float t2 = v2 + b0; v2 = (t2 > 20.f) ? t2 : __logf(1.f + __expf(t2));
                float t3 = v3 + b1; v3 = (t3 > 20.f) ? t3 : __logf(1.f + __expf(t3));
            } else if (EPI == 2) {
                const float2 r0 = *reinterpret_cast<const float2*>(resid + (size_t)m*N + n);
                const float2 r1 = *reinterpret_cast<const float2*>(resid + (size_t)(m+8)*N + n);
                v0 += r0.x; v1 += r0.y; v2 += r1.x; v3 += r1.y;
            }
            *reinterpret_cast<float2*>(C + (size_t)m*N + n)     = make_float2(v0, v1);
            *reinterpret_cast<float2*>(C + (size_t)(m+8)*N + n) = make_float2(v2, v3);
        }
    }
}

#define SMEM_W2 (2*((128*TILE_ROW_BYTES) + (128*TILE_ROW_BYTES)))  // 73728
#define SMEM_W1 (2*(( 64*TILE_ROW_BYTES) + (128*TILE_ROW_BYTES)))  // 55296

// ---------------- RMSNorm ----------------
__global__ __launch_bounds__(256) void rmsnorm_kernel(
    const float* __restrict__ x, const float* __restrict__ w, float* __restrict__ xn)
{
    __shared__ float red[8];
    __shared__ float s_scale;
    int m = blockIdx.x, tid = threadIdx.x;
    float4 v = reinterpret_cast<const float4*>(x + (size_t)m*DMODEL)[tid];
    float s = v.x*v.x + v.y*v.y + v.z*v.z + v.w*v.w;
    #pragma unroll
    for (int o = 16; o > 0; o >>= 1) s += __shfl_xor_sync(0xffffffffu, s, o);
    if ((tid & 31) == 0) red[tid >> 5] = s;
    __syncthreads();
    if (tid < 32) {
        float t = (tid < 8) ? red[tid] : 0.f;
        #pragma unroll
        for (int o = 4; o > 0; o >>= 1) t += __shfl_xor_sync(0xffffffffu, t, o);
        if (tid == 0) s_scale = rsqrtf(t * (1.0f/DMODEL) + 1e-6f);
    }
    __syncthreads();
    float sc = s_scale;
    float4 wv = reinterpret_cast<const float4*>(w)[tid];
    float4 o;
    o.x = v.x*sc*wv.x; o.y = v.y*sc*wv.y; o.z = v.z*sc*wv.z; o.w = v.w*sc*wv.w;
    reinterpret_cast<float4*>(xn + (size_t)m*DMODEL)[tid] = o;
}

// ---------------- Depthwise causal conv (k=4) + bias + SiLU ----------------
__global__ __launch_bounds__(256) void conv_silu_kernel(
    const float* __restrict__ xz, const float* __restrict__ cw,
    const float* __restrict__ cb, float* __restrict__ uc)
{
    int idx = blockIdx.x * 256 + threadIdx.x;
    int d = idx & (DINNER-1);
    int m = idx >> 11;
    int l = m & (LL-1);
    float4 wv = reinterpret_cast<const float4*>(cw)[d];
    const float* up = xz + (size_t)m * (2*DINNER) + d;
    float acc = cb[d];
    acc = fmaf(up[0], wv.w, acc);
    if (l >= 1) acc = fmaf(up[-1*(2*DINNER)], wv.z, acc);
    if (l >= 2) acc = fmaf(up[-2*(2*DINNER)], wv.y, acc);
    if (l >= 3) acc = fmaf(up[-3*(2*DINNER)], wv.x, acc);
    uc[idx] = acc / (1.f + __expf(-acc));
}

// ---------------- Selective scan ----------------
#define SCL 64
#define SWP 8
__global__ __launch_bounds__(256) void scan_kernel(
    const float* __restrict__ xz,  const float* __restrict__ uc,
    const float* __restrict__ dbl, const float* __restrict__ dt,
    const float* __restrict__ A_log, const float* __restrict__ D_param,
    float* __restrict__ y)
{
    __shared__ float sB [SCL][DSTATE];
    __shared__ float sC [SCL][DSTATE];
    __shared__ float sdt[SCL][SWP];
    __shared__ float su [SCL][SWP];
    __shared__ float sz [SCL][SWP];
    __shared__ float sy [SCL][SWP];

    const int b    = blockIdx.y;
    const int d0   = blockIdx.x * SWP;
    const int tid  = threadIdx.x;
    const int w    = tid >> 5;
    const int lane = tid & 31;
    const int d    = d0 + w;
    const int mb   = b * LL;

    const float Aln = -__expf(A_log[d*DSTATE + lane]);
    const float Dd  = D_param[d];
    float h = 0.f;

    for (int c0 = 0; c0 < LL; c0 += SCL) {
        for (int idx = tid; idx < SCL*DSTATE; idx += 256) {
            int t = idx >> 5, n = idx & 31;
            int m = mb + c0 + t;
            sB[t][n] = dbl[(size_t)m*XPROJ_N + DTRANK + n];
            sC[t][n] = dbl[(size_t)m*XPROJ_N + DTRANK + DSTATE + n];
        }
        for (int idx = tid; idx < SCL*SWP; idx += 256) {
            int t = idx >> 3, dd = idx & 7;
            int m = mb + c0 + t;
            sdt[t][dd] = dt[(size_t)m*DINNER + d0 + dd];
            su [t][dd] = uc[(size_t)m*DINNER + d0 + dd];
            sz [t][dd] = xz[(size_t)m*(2*DINNER) + DINNER + d0 + dd];
        }
        __syncthreads();

        #pragma unroll 4
        for (int t = 0; t < SCL; ++t) {
            float dtv = sdt[t][w];
            float uv  = su[t][w];
            float dA  = __expf(dtv * Aln);
            h = fmaf(dA, h, (dtv * uv) * sB[t][lane]);
            float p = h * sC[t][lane];
            p += __shfl_xor_sync(0xffffffffu, p, 16);
            p += __shfl_xor_sync(0xffffffffu, p, 8);
            p += __shfl_xor_sync(0xffffffffu, p, 4);
            p += __shfl_xor_sync(0xffffffffu, p, 2);
            p += __shfl_xor_sync(0xffffffffu, p, 1);
            if (lane == 0) {
                float yv = p + uv * Dd;
                float zv = sz[t][w];
                sy[t][w] = yv * (zv / (1.f + __expf(-zv)));
            }
        }
        __syncthreads();

        for (int idx = tid; idx < SCL*SWP; idx += 256) {
            int t = idx >> 3, dd = idx & 7;
            y[(size_t)(mb + c0 + t)*DINNER + d0 + dd] = sy[t][dd];
        }
    }
}

// ---------------- Launch ----------------
extern "C" void kernel_launch(void* const* d_in, const int* in_sizes, int n_in,
                              void* d_out, int out_size)
{
    const float* x         = (const float*)d_in[0];
    const float* norm_w    = (const float*)d_in[1];
    const float* in_proj_w = (const float*)d_in[2];
    const float* conv_w    = (const float*)d_in[3];
    const float* conv_b    = (const float*)d_in[4];
    const float* x_proj_w  = (const float*)d_in[5];
    const float* dt_proj_w = (const float*)d_in[6];
    const float* dt_proj_b = (const float*)d_in[7];
    const float* A_log     = (const float*)d_in[8];
    const float* D_param   = (const float*)d_in[9];
    const float* out_proj_w= (const float*)d_in[10];
    float* out = (float*)d_out;

    float *p_xn, *p_xz, *p_uc, *p_dbl, *p_dt, *p_y;
    cudaGetSymbolAddress((void**)&p_xn,  g_xn);
    cudaGetSymbolAddress((void**)&p_xz,  g_xz);
    cudaGetSymbolAddress((void**)&p_uc,  g_uc);
    cudaGetSymbolAddress((void**)&p_dbl, g_dbl);
    cudaGetSymbolAddress((void**)&p_dt,  g_dt);
    cudaGetSymbolAddress((void**)&p_y,   g_y);
    cudaFuncSetAttribute(mma_gemm<2,0>, cudaFuncAttributeMaxDynamicSharedMemorySize, SMEM_W2);
    cudaFuncSetAttribute(mma_gemm<1,0>, cudaFuncAttributeMaxDynamicSharedMemorySize, SMEM_W1);
    cudaFuncSetAttribute(mma_gemm<2,1>, cudaFuncAttributeMaxDynamicSharedMemorySize, SMEM_W2);
    cudaFuncSetAttribute(mma_gemm<2,2>, cudaFuncAttributeMaxDynamicSharedMemorySize, SMEM_W2);

    // 1) RMSNorm
    rmsnorm_kernel<<<MM, 256>>>(x, norm_w, p_xn);

    // 2) in_proj: xz[8192,4096] = xn @ in_proj_w^T
    mma_gemm<2,0><<<dim3((2*DINNER)/128, MM/128), 512, SMEM_W2>>>(
        p_xn, DMODEL, in_proj_w, p_xz, 2*DINNER, DMODEL, nullptr, nullptr);

    // 3) conv + silu
    conv_silu_kernel<<<(MM*DINNER)/256, 256>>>(p_xz, conv_w, conv_b, p_uc);

    // 4) x_proj: dbl[8192,128] = uc @ x_proj_w^T  (BM=64: 128 CTAs x 16 warps)
    mma_gemm<1,0><<<dim3(XPROJ_N/128, MM/64), 512, SMEM_W1>>>(
        p_uc, DINNER, x_proj_w, p_dbl, XPROJ_N, DINNER, nullptr, nullptr);

    // 5) dt_proj + softplus (A = first 64 cols of dbl, lda=128)
    mma_gemm<2,1><<<dim3(DINNER/128, MM/128), 512, SMEM_W2>>>(
        p_dbl, XPROJ_N, dt_proj_w, p_dt, DINNER, DTRANK, dt_proj_b, nullptr);

    // 6) selective scan + skip + gate
    scan_kernel<<<dim3(DINNER/SWP, BB), 256>>>(
        p_xz, p_uc, p_dbl, p_dt, A_log, D_param, p_y);

    // 7) out_proj + residual
    mma_gemm<2,2><<<dim3(DMODEL/128, MM/128), 512, SMEM_W2>>>(
        p_y, DINNER, out_proj_w, out, DMODEL, DINNER, nullptr, x);
}

// round 14
// speedup vs baseline: 1.4984x; 1.4984x over previous
#include <cuda_runtime.h>
#include <cuda_bf16.h>
#include <math.h>
#include <stdint.h>

// ---------------- Problem constants ----------------
#define BB 4
#define LL 2048
#define DMODEL 1024
#define DINNER 2048
#define DSTATE 32
#define DTRANK 64
#define MM (BB*LL)          // 8192 rows
#define XPROJ_N 128

// ---------------- Scratch ----------------
__device__ float g_xn [MM*DMODEL];
__device__ float g_xz [MM*(2*DINNER)];
__device__ float g_uc [MM*DINNER];
__device__ float g_dbl[MM*XPROJ_N];
__device__ float g_dt [MM*DINNER];
__device__ float g_y  [MM*DINNER];

// ---------------- helpers ----------------
__device__ __forceinline__ uint32_t smem_u32(const void* p){
    uint32_t a;
    asm("{ .reg .u64 t; cvta.to.shared.u64 t, %1; cvt.u32.u64 %0, t; }" : "=r"(a) : "l"(p));
    return a;
}
__device__ __forceinline__ float ex2f(float x){
    float r; asm("ex2.approx.f32 %0, %1;" : "=f"(r) : "f"(x)); return r;
}
__device__ __forceinline__ void mma_tf32(float* c, const uint32_t* a, const uint32_t* b){
    asm volatile(
        "mma.sync.aligned.m16n8k8.row.col.f32.tf32.tf32.f32 "
        "{%0,%1,%2,%3}, {%4,%5,%6,%7}, {%8,%9}, {%0,%1,%2,%3};"
        : "+f"(c[0]), "+f"(c[1]), "+f"(c[2]), "+f"(c[3])
        : "r"(a[0]), "r"(a[1]), "r"(a[2]), "r"(a[3]), "r"(b[0]), "r"(b[1]));
}
__device__ __forceinline__ void ldsm4(uint32_t* r, uint32_t addr){
    asm volatile("ldmatrix.sync.aligned.m8n8.x4.shared.b16 {%0,%1,%2,%3}, [%4];"
        : "=r"(r[0]), "=r"(r[1]), "=r"(r[2]), "=r"(r[3]) : "r"(addr));
}

// ---------------- tf32 mma.sync GEMM (3-stage, 1 barrier/ktile) -- round-11 core
// C[m,n] = sum_k A[m,k]*Bw[n,k]; A row-major lda, Bw row-major [N,K].
// BM=32*MT, BN=128, BK=32. 256 threads = 8 warps (2 m x 4 n).
// EPI: 0 none, 1 softplus(acc+bias[n]), 2 acc+resid.
#define GP 36                      // smem row pitch in floats
#define TILE_ROW_BYTES (GP*4)      // 144

template<int MT, int EPI>
__global__ __launch_bounds__(256, 2) void mma_gemm(
    const float* __restrict__ A, int lda,
    const float* __restrict__ Bw,
    float* __restrict__ C,
    int N, int K,
    const float* __restrict__ bias,
    const float* __restrict__ resid)
{
    constexpr int BM  = 32*MT;
    constexpr int SAB = BM * TILE_ROW_BYTES;
    constexpr int SBB = 128 * TILE_ROW_BYTES;
    constexpr int STG = SAB + SBB;

    extern __shared__ char dynsmem[];
    const uint32_t sm32 = smem_u32(dynsmem);

    const int tid  = threadIdx.x;
    const int wid  = tid >> 5, lane = tid & 31;
    const int g    = lane >> 2;
    const int c2   = (lane & 3) * 2;
    const int wm   = (wid >> 2) * (16*MT);
    const int wn   = (wid & 3) * 32;
    const int m0   = blockIdx.y * BM;
    const int n0   = blockIdx.x * 128;

    const int lrow = tid >> 3;
    const int lk16 = (tid & 7) * 16;

    const float* Ap0 = A  + (size_t)(m0 + lrow) * lda + (lk16 >> 2);
    const float* Bp0 = Bw + (size_t)(n0 + lrow) * K   + (lk16 >> 2);

    const uint32_t aoff = ((wm + (lane & 15))*GP + (lane >> 4)*4) * 4;
    const uint32_t boff = ((wn + 8*(lane >> 4) + (lane & 7))*GP + ((lane >> 3) & 1)*4) * 4;

    float acc[MT][4][4];
    #pragma unroll
    for (int i = 0; i < MT; ++i)
        #pragma unroll
        for (int j = 0; j < 4; ++j)
            #pragma unroll
            for (int q = 0; q < 4; ++q) acc[i][j][q] = 0.f;

    const int KT = K / 32;

    // prologue: tiles 0 and 1 -> stages 0 and 1
    #pragma unroll
    for (int p = 0; p < 2; ++p) {
        if (p < KT) {
            const uint32_t da = sm32 + p*STG;
            const float* Apn = Ap0 + p*32;
            const float* Bpn = Bp0 + p*32;
            #pragma unroll
            for (int i = 0; i < MT; ++i)
                asm volatile("cp.async.cg.shared.global [%0], [%1], 16;"
                    :: "r"(da + (lrow + 32*i)*TILE_ROW_BYTES + lk16),
                       "l"(Apn + (size_t)(32*i)*lda));
            #pragma unroll
            for (int i = 0; i < 4; ++i)
                asm volatile("cp.async.cg.shared.global [%0], [%1], 16;"
                    :: "r"(da + SAB + (lrow + 32*i)*TILE_ROW_BYTES + lk16),
                       "l"(Bpn + (size_t)(32*i)*K));
            asm volatile("cp.async.commit_group;" ::: "memory");
        }
    }

    int s = 0, sp = 2;
    for (int kt = 0; kt < KT; ++kt) {
        if (kt + 1 < KT) asm volatile("cp.async.wait_group 1;" ::: "memory");
        else             asm volatile("cp.async.wait_group 0;" ::: "memory");
        __syncthreads();

        if (kt + 2 < KT) {
            const uint32_t da = sm32 + sp*STG;
            const float* Apn = Ap0 + (kt + 2)*32;
            const float* Bpn = Bp0 + (kt + 2)*32;
            #pragma unroll
            for (int i = 0; i < MT; ++i)
                asm volatile("cp.async.cg.shared.global [%0], [%1], 16;"
                    :: "r"(da + (lrow + 32*i)*TILE_ROW_BYTES + lk16),
                       "l"(Apn + (size_t)(32*i)*lda));
            #pragma unroll
            for (int i = 0; i < 4; ++i)
                asm volatile("cp.async.cg.shared.global [%0], [%1], 16;"
                    :: "r"(da + SAB + (lrow + 32*i)*TILE_ROW_BYTES + lk16),
                       "l"(Bpn + (size_t)(32*i)*K));
            asm volatile("cp.async.commit_group;" ::: "memory");
        }

        const uint32_t sA = sm32 + s*STG;
        const uint32_t sB = sA + SAB;
        #pragma unroll
        for (int k8 = 0; k8 < 4; ++k8) {
            const uint32_t kbyte = k8 * 32;
            uint32_t afr[MT][4];
            #pragma unroll
            for (int mt = 0; mt < MT; ++mt)
                ldsm4(afr[mt], sA + aoff + mt*(16*TILE_ROW_BYTES) + kbyte);
            uint32_t bfr[4][2];
            {
                uint32_t t0[4], t1[4];
                ldsm4(t0, sB + boff + kbyte);
                ldsm4(t1, sB + boff + 16*TILE_ROW_BYTES + kbyte);
                bfr[0][0]=t0[0]; bfr[0][1]=t0[1]; bfr[1][0]=t0[2]; bfr[1][1]=t0[3];
                bfr[2][0]=t1[0]; bfr[2][1]=t1[1]; bfr[3][0]=t1[2]; bfr[3][1]=t1[3];
            }
            #pragma unroll
            for (int mt = 0; mt < MT; ++mt)
                #pragma unroll
                for (int nt = 0; nt < 4; ++nt)
                    mma_tf32(acc[mt][nt], afr[mt], bfr[nt]);
        }

        s  = (s  == 2) ? 0 : s + 1;
        sp = (sp == 2) ? 0 : sp + 1;
    }

    #pragma unroll
    for (int mt = 0; mt < MT; ++mt) {
        #pragma unroll
        for (int nt = 0; nt < 4; ++nt) {
            const int m = m0 + wm + mt*16 + g;
            const int n = n0 + wn + nt*8 + c2;
            float v0 = acc[mt][nt][0], v1 = acc[mt][nt][1];
            float v2 = acc[mt][nt][2], v3 = acc[mt][nt][3];
            if (EPI == 1) {
                float b0 = bias[n], b1 = bias[n+1];
                float t0 = v0 + b0; v0 = (t0 > 20.f) ? t0 : __logf(1.f + __expf(t0));
                float t1 = v1 + b1; v1 = (t1 > 20.f) ? t1 : __logf(1.f + __expf(t1));
                float t2 = v2 + b0; v2 = (t2 > 20.f) ? t2 : __logf(1.f + __expf(t2));
                float t3 = v3 + b1; v3 = (t3 > 20.f) ? t3 : __logf(1.f + __expf(t3));
            } else if (EPI == 2) {
                const float2 r0 = *reinterpret_cast<const float2*>(resid + (size_t)m*N + n);
                const float2 r1 = *reinterpret_cast<const float2*>(resid + (size_t)(m+8)*N + n);
                v0 += r0.x; v1 += r0.y; v2 += r1.x; v3 += r1.y;
            }
            *reinterpret_cast<float2*>(C + (size_t)m*N + n)     = make_float2(v0, v1);
            *reinterpret_cast<float2*>(C + (size_t)(m+8)*N + n) = make_float2(v2, v3);
        }
    }
}

#define SMEM_MT4 (3*((128*TILE_ROW_BYTES) + (128*TILE_ROW_BYTES)))  // 110592
#define SMEM_MT2 (3*(( 64*TILE_ROW_BYTES) + (128*TILE_ROW_BYTES)))  // 82944

// ---------------- RMSNorm ----------------
__global__ __launch_bounds__(256) void rmsnorm_kernel(
    const float* __restrict__ x, const float* __restrict__ w, float* __restrict__ xn)
{
    __shared__ float red[8];
    __shared__ float s_scale;
    int m = blockIdx.x, tid = threadIdx.x;
    float4 v = reinterpret_cast<const float4*>(x + (size_t)m*DMODEL)[tid];
    float s = v.x*v.x + v.y*v.y + v.z*v.z + v.w*v.w;
    #pragma unroll
    for (int o = 16; o > 0; o >>= 1) s += __shfl_xor_sync(0xffffffffu, s, o);
    if ((tid & 31) == 0) red[tid >> 5] = s;
    __syncthreads();
    if (tid < 32) {
        float t = (tid < 8) ? red[tid] : 0.f;
        #pragma unroll
        for (int o = 4; o > 0; o >>= 1) t += __shfl_xor_sync(0xffffffffu, t, o);
        if (tid == 0) s_scale = rsqrtf(t * (1.0f/DMODEL) + 1e-6f);
    }
    __syncthreads();
    float sc = s_scale;
    float4 wv = reinterpret_cast<const float4*>(w)[tid];
    float4 o;
    o.x = v.x*sc*wv.x; o.y = v.y*sc*wv.y; o.z = v.z*sc*wv.z; o.w = v.w*sc*wv.w;
    reinterpret_cast<float4*>(xn + (size_t)m*DMODEL)[tid] = o;
}

// ---------------- Depthwise causal conv (k=4) + bias + SiLU ----------------
__global__ __launch_bounds__(256) void conv_silu_kernel(
    const float* __restrict__ xz, const float* __restrict__ cw,
    const float* __restrict__ cb, float* __restrict__ uc)
{
    int idx = blockIdx.x * 256 + threadIdx.x;
    int d = idx & (DINNER-1);
    int m = idx >> 11;
    int l = m & (LL-1);
    float4 wv = reinterpret_cast<const float4*>(cw)[d];
    const float* up = xz + (size_t)m * (2*DINNER) + d;
    float acc = cb[d];
    acc = fmaf(up[0], wv.w, acc);
    if (l >= 1) acc = fmaf(up[-1*(2*DINNER)], wv.z, acc);
    if (l >= 2) acc = fmaf(up[-2*(2*DINNER)], wv.y, acc);
    if (l >= 3) acc = fmaf(up[-3*(2*DINNER)], wv.x, acc);
    uc[idx] = acc / (1.f + __expf(-acc));
}

// ---------------- Selective scan: 8 lanes/channel, 4 states/lane --------------
// CTA: 256 thr = 8 warps = 32 channels. Chunk of SCH timesteps staged in smem.
// Gating (silu(z)) moved to the dense store pass.
#define SCH 64
__global__ __launch_bounds__(256) void scan_kernel(
    const float* __restrict__ xz,  const float* __restrict__ uc,
    const float* __restrict__ dbl, const float* __restrict__ dt,
    const float* __restrict__ A_log, const float* __restrict__ D_param,
    float* __restrict__ y)
{
    __shared__ float sB [SCH][DSTATE];
    __shared__ float sC [SCH][DSTATE];
    __shared__ float sdt[SCH][32];
    __shared__ float su [SCH][32];
    __shared__ float sy [SCH][32];

    const int b    = blockIdx.y;
    const int d0   = blockIdx.x * 32;
    const int tid  = threadIdx.x;
    const int w    = tid >> 5;
    const int lane = tid & 31;
    const int grp  = lane >> 3;        // 0..3 : channel within warp
    const int gl   = lane & 7;         // lane within channel group
    const int c    = w*4 + grp;        // channel in CTA (0..31)
    const int d    = d0 + c;
    const int n0   = gl*4;             // first of 4 states owned
    const int mb   = b * LL;

    // per-lane constants: 4 states' log2-space decay coefficients
    float k0, k1, k2, k3;
    {
        const float4 al = *reinterpret_cast<const float4*>(A_log + d*DSTATE + n0);
        const float l2e = 1.44269504f;
        k0 = -__expf(al.x) * l2e; k1 = -__expf(al.y) * l2e;
        k2 = -__expf(al.z) * l2e; k3 = -__expf(al.w) * l2e;
    }
    const float Dd = D_param[d];
    float h0 = 0.f, h1 = 0.f, h2 = 0.f, h3 = 0.f;

    for (int c0 = 0; c0 < LL; c0 += SCH) {
        // stage B, C: warp w handles rows t = w, w+8, ...; lane covers n
        for (int idx = tid; idx < SCH*DSTATE; idx += 256) {
            int t = idx >> 5, n = idx & 31;
            int m = mb + c0 + t;
            sB[t][n] = dbl[(size_t)m*XPROJ_N + DTRANK + n];
            sC[t][n] = dbl[(size_t)m*XPROJ_N + DTRANK + DSTATE + n];
        }
        // stage dt, u (coalesced 128B rows)
        for (int idx = tid; idx < SCH*32; idx += 256) {
            int t = idx >> 5, cc = idx & 31;
            int m = mb + c0 + t;
            sdt[t][cc] = dt[(size_t)m*DINNER + d0 + cc];
            su [t][cc] = uc[(size_t)m*DINNER + d0 + cc];
        }
        __syncthreads();

        #pragma unroll 2
        for (int t = 0; t < SCH; ++t) {
            const float dtv = sdt[t][c];
            const float uv  = su[t][c];
            const float dtu = dtv * uv;
            const float4 B4 = *reinterpret_cast<const float4*>(&sB[t][n0]);
            const float4 C4 = *reinterpret_cast<const float4*>(&sC[t][n0]);
            const float a0 = ex2f(dtv * k0);
            const float a1 = ex2f(dtv * k1);
            const float a2 = ex2f(dtv * k2);
            const float a3 = ex2f(dtv * k3);
            h0 = fmaf(a0, h0, dtu * B4.x);
            h1 = fmaf(a1, h1, dtu * B4.y);
            h2 = fmaf(a2, h2, dtu * B4.z);
            h3 = fmaf(a3, h3, dtu * B4.w);
            float p = h0 * C4.x;
            p = fmaf(h1, C4.y, p);
            p = fmaf(h2, C4.z, p);
            p = fmaf(h3, C4.w, p);
            p += __shfl_xor_sync(0xffffffffu, p, 4);
            p += __shfl_xor_sync(0xffffffffu, p, 2);
            p += __shfl_xor_sync(0xffffffffu, p, 1);
            if (gl == 0) sy[t][c] = fmaf(uv, Dd, p);   // pre-gate value
        }
        __syncthreads();

        // dense store pass: apply silu(z) gating and write y (coalesced)
        for (int idx = tid; idx < SCH*32; idx += 256) {
            int t = idx >> 5, cc = idx & 31;
            int m = mb + c0 + t;
            float zv = xz[(size_t)m*(2*DINNER) + DINNER + d0 + cc];
            float yv = sy[t][cc];
            y[(size_t)m*DINNER + d0 + cc] = yv * (zv / (1.f + __expf(-zv)));
        }
    }
}

// ---------------- Launch ----------------
extern "C" void kernel_launch(void* const* d_in, const int* in_sizes, int n_in,
                              void* d_out, int out_size)
{
    const float* x         = (const float*)d_in[0];
    const float* norm_w    = (const float*)d_in[1];
    const float* in_proj_w = (const float*)d_in[2];
    const float* conv_w    = (const float*)d_in[3];
    const float* conv_b    = (const float*)d_in[4];
    const float* x_proj_w  = (const float*)d_in[5];
    const float* dt_proj_w = (const float*)d_in[6];
    const float* dt_proj_b = (const float*)d_in[7];
    const float* A_log     = (const float*)d_in[8];
    const float* D_param   = (const float*)d_in[9];
    const float* out_proj_w= (const float*)d_in[10];
    float* out = (float*)d_out;

    float *p_xn, *p_xz, *p_uc, *p_dbl, *p_dt, *p_y;
    cudaGetSymbolAddress((void**)&p_xn,  g_xn);
    cudaGetSymbolAddress((void**)&p_xz,  g_xz);
    cudaGetSymbolAddress((void**)&p_uc,  g_uc);
    cudaGetSymbolAddress((void**)&p_dbl, g_dbl);
    cudaGetSymbolAddress((void**)&p_dt,  g_dt);
    cudaGetSymbolAddress((void**)&p_y,   g_y);
    cudaFuncSetAttribute(mma_gemm<4,0>, cudaFuncAttributeMaxDynamicSharedMemorySize, SMEM_MT4);
    cudaFuncSetAttribute(mma_gemm<2,0>, cudaFuncAttributeMaxDynamicSharedMemorySize, SMEM_MT2);
    cudaFuncSetAttribute(mma_gemm<4,1>, cudaFuncAttributeMaxDynamicSharedMemorySize, SMEM_MT4);
    cudaFuncSetAttribute(mma_gemm<4,2>, cudaFuncAttributeMaxDynamicSharedMemorySize, SMEM_MT4);

    // 1) RMSNorm
    rmsnorm_kernel<<<MM, 256>>>(x, norm_w, p_xn);

    // 2) in_proj
    mma_gemm<4,0><<<dim3((2*DINNER)/128, MM/128), 256, SMEM_MT4>>>(
        p_xn, DMODEL, in_proj_w, p_xz, 2*DINNER, DMODEL, nullptr, nullptr);

    // 3) conv + silu
    conv_silu_kernel<<<(MM*DINNER)/256, 256>>>(p_xz, conv_w, conv_b, p_uc);

    // 4) x_proj (BM=64, grid 128 — round-10 best at 49.8us)
    mma_gemm<2,0><<<dim3(XPROJ_N/128, MM/64), 256, SMEM_MT2>>>(
        p_uc, DINNER, x_proj_w, p_dbl, XPROJ_N, DINNER, nullptr, nullptr);

    // 5) dt_proj + softplus
    mma_gemm<4,1><<<dim3(DINNER/128, MM/128), 256, SMEM_MT4>>>(
        p_dbl, XPROJ_N, dt_proj_w, p_dt, DINNER, DTRANK, dt_proj_b, nullptr);

    // 6) selective scan + skip + gate (restructured: 8 lanes/channel)
    scan_kernel<<<dim3(DINNER/32, BB), 256>>>(
        p_xz, p_uc, p_dbl, p_dt, A_log, D_param, p_y);

    // 7) out_proj + residual
    mma_gemm<4,2><<<dim3(DMODEL/128, MM/128), 256, SMEM_MT4>>>(
        p_y, DINNER, out_proj_w, out, DMODEL, DINNER, nullptr, x);
}

// round 15
// speedup vs baseline: 1.9147x; 1.2778x over previous
#include <cuda_runtime.h>
#include <cuda_bf16.h>
#include <cuda_fp16.h>
#include <math.h>
#include <stdint.h>

// ---------------- Problem constants ----------------
#define BB 4
#define LL 2048
#define DMODEL 1024
#define DINNER 2048
#define DSTATE 32
#define DTRANK 64
#define MM (BB*LL)          // 8192 rows
#define XPROJ_N 128

// ---------------- Scratch ----------------
__device__ float  g_xz [MM*(2*DINNER)];
__device__ float  g_dbl[MM*XPROJ_N];
__device__ float  g_dt [MM*DINNER];
__device__ __half g_xn_h [MM*DMODEL];
__device__ __half g_uc_h [MM*DINNER];
__device__ __half g_y_h  [MM*DINNER];
__device__ __half g_wip_h[(2*DINNER)*DMODEL];
__device__ __half g_wxp_h[XPROJ_N*DINNER];
__device__ __half g_wop_h[DMODEL*DINNER];

// ---------------- helpers ----------------
__device__ __forceinline__ uint32_t smem_u32(const void* p){
    uint32_t a;
    asm("{ .reg .u64 t; cvta.to.shared.u64 t, %1; cvt.u32.u64 %0, t; }" : "=r"(a) : "l"(p));
    return a;
}
__device__ __forceinline__ float ex2f(float x){
    float r; asm("ex2.approx.f32 %0, %1;" : "=f"(r) : "f"(x)); return r;
}
__device__ __forceinline__ void mma_tf32(float* c, const uint32_t* a, const uint32_t* b){
    asm volatile(
        "mma.sync.aligned.m16n8k8.row.col.f32.tf32.tf32.f32 "
        "{%0,%1,%2,%3}, {%4,%5,%6,%7}, {%8,%9}, {%0,%1,%2,%3};"
        : "+f"(c[0]), "+f"(c[1]), "+f"(c[2]), "+f"(c[3])
        : "r"(a[0]), "r"(a[1]), "r"(a[2]), "r"(a[3]), "r"(b[0]), "r"(b[1]));
}
__device__ __forceinline__ void mma_f16(float* c, const uint32_t* a, const uint32_t* b){
    asm volatile(
        "mma.sync.aligned.m16n8k16.row.col.f32.f16.f16.f32 "
        "{%0,%1,%2,%3}, {%4,%5,%6,%7}, {%8,%9}, {%0,%1,%2,%3};"
        : "+f"(c[0]), "+f"(c[1]), "+f"(c[2]), "+f"(c[3])
        : "r"(a[0]), "r"(a[1]), "r"(a[2]), "r"(a[3]), "r"(b[0]), "r"(b[1]));
}
__device__ __forceinline__ void ldsm4(uint32_t* r, uint32_t addr){
    asm volatile("ldmatrix.sync.aligned.m8n8.x4.shared.b16 {%0,%1,%2,%3}, [%4];"
        : "=r"(r[0]), "=r"(r[1]), "=r"(r[2]), "=r"(r[3]) : "r"(addr));
}

// ---------------- f32 -> f16 convert (weights) ----------------
__global__ __launch_bounds__(256) void cvt_h_kernel(
    const float* __restrict__ src, __half* __restrict__ dst, int n4)
{
    int i = blockIdx.x * 256 + threadIdx.x;
    if (i < n4) {
        float4 v = reinterpret_cast<const float4*>(src)[i];
        __half2* po = reinterpret_cast<__half2*>(dst) + i*2;
        po[0] = __floats2half2_rn(v.x, v.y);
        po[1] = __floats2half2_rn(v.z, v.w);
    }
}

// ---------------- fp16 mma.sync GEMM (3-stage, 1 barrier/ktile) ---------------
// C[m,n] = sum_k A[m,k]*Bw[n,k]; A,Bw f16 row-major, C f32.
// BM=32*MT, BN=128, BK=64 halves (128B rows, pitch 144B). 256 thr, 8 warps 2x4.
// EPI: 0 none, 2 acc+resid.
#define GPH 144   // f16 row pitch bytes

template<int MT, int EPI>
__global__ __launch_bounds__(256, 2) void hgemm(
    const __half* __restrict__ A, int lda,
    const __half* __restrict__ Bw,
    float* __restrict__ C,
    int N, int K,
    const float* __restrict__ resid)
{
    constexpr int BM  = 32*MT;
    constexpr int SAB = BM * GPH;
    constexpr int SBB = 128 * GPH;
    constexpr int STG = SAB + SBB;

    extern __shared__ char dynsmem[];
    const uint32_t sm32 = smem_u32(dynsmem);

    const int tid  = threadIdx.x;
    const int wid  = tid >> 5, lane = tid & 31;
    const int g    = lane >> 2;
    const int c2   = (lane & 3) * 2;
    const int wm   = (wid >> 2) * (16*MT);
    const int wn   = (wid & 3) * 32;
    const int m0   = blockIdx.y * BM;
    const int n0   = blockIdx.x * 128;

    const int lrow = tid >> 3;           // 0..31
    const int lh16 = (tid & 7) * 8;      // half offset (16B chunk)

    const __half* Ap0 = A  + (size_t)(m0 + lrow) * lda + lh16;
    const __half* Bp0 = Bw + (size_t)(n0 + lrow) * K   + lh16;

    // ldmatrix base byte offsets (within a stage)
    const uint32_t aoffB = (uint32_t)(wm + (lane & 15))*GPH + (lane >> 4)*16;
    const uint32_t boffB = (uint32_t)(wn + 8*(lane >> 4) + (lane & 7))*GPH + ((lane >> 3) & 1)*16;

    float acc[MT][4][4];
    #pragma unroll
    for (int i = 0; i < MT; ++i)
        #pragma unroll
        for (int j = 0; j < 4; ++j)
            #pragma unroll
            for (int q = 0; q < 4; ++q) acc[i][j][q] = 0.f;

    const int KT = K / 64;

    // prologue: tiles 0,1 -> stages 0,1
    #pragma unroll
    for (int p = 0; p < 2; ++p) {
        if (p < KT) {
            const uint32_t da = sm32 + p*STG;
            const __half* Apn = Ap0 + p*64;
            const __half* Bpn = Bp0 + p*64;
            #pragma unroll
            for (int i = 0; i < MT; ++i)
                asm volatile("cp.async.cg.shared.global [%0], [%1], 16;"
                    :: "r"(da + (lrow + 32*i)*GPH + (tid & 7)*16),
                       "l"(Apn + (size_t)(32*i)*lda));
            #pragma unroll
            for (int i = 0; i < 4; ++i)
                asm volatile("cp.async.cg.shared.global [%0], [%1], 16;"
                    :: "r"(da + SAB + (lrow + 32*i)*GPH + (tid & 7)*16),
                       "l"(Bpn + (size_t)(32*i)*K));
            asm volatile("cp.async.commit_group;" ::: "memory");
        }
    }

    int s = 0, sp = 2;
    for (int kt = 0; kt < KT; ++kt) {
        if (kt + 1 < KT) asm volatile("cp.async.wait_group 1;" ::: "memory");
        else             asm volatile("cp.async.wait_group 0;" ::: "memory");
        __syncthreads();

        if (kt + 2 < KT) {
            const uint32_t da = sm32 + sp*STG;
            const __half* Apn = Ap0 + (kt + 2)*64;
            const __half* Bpn = Bp0 + (kt + 2)*64;
            #pragma unroll
            for (int i = 0; i < MT; ++i)
                asm volatile("cp.async.cg.shared.global [%0], [%1], 16;"
                    :: "r"(da + (lrow + 32*i)*GPH + (tid & 7)*16),
                       "l"(Apn + (size_t)(32*i)*lda));
            #pragma unroll
            for (int i = 0; i < 4; ++i)
                asm volatile("cp.async.cg.shared.global [%0], [%1], 16;"
                    :: "r"(da + SAB + (lrow + 32*i)*GPH + (tid & 7)*16),
                       "l"(Bpn + (size_t)(32*i)*K));
            asm volatile("cp.async.commit_group;" ::: "memory");
        }

        const uint32_t sA = sm32 + s*STG;
        const uint32_t sB = sA + SAB;
        #pragma unroll
        for (int k16 = 0; k16 < 4; ++k16) {
            const uint32_t kbyte = k16 * 32;   // 16 halves
            uint32_t afr[MT][4];
            #pragma unroll
            for (int mt = 0; mt < MT; ++mt)
                ldsm4(afr[mt], sA + aoffB + mt*(16*GPH) + kbyte);
            uint32_t bfr[4][2];
            {
                uint32_t t0[4], t1[4];
                ldsm4(t0, sB + boffB + kbyte);              // nt0, nt1
                ldsm4(t1, sB + boffB + 16*GPH + kbyte);     // nt2, nt3
                bfr[0][0]=t0[0]; bfr[0][1]=t0[1]; bfr[1][0]=t0[2]; bfr[1][1]=t0[3];
                bfr[2][0]=t1[0]; bfr[2][1]=t1[1]; bfr[3][0]=t1[2]; bfr[3][1]=t1[3];
            }
            #pragma unroll
            for (int mt = 0; mt < MT; ++mt)
                #pragma unroll
                for (int nt = 0; nt < 4; ++nt)
                    mma_f16(acc[mt][nt], afr[mt], bfr[nt]);
        }

        s  = (s  == 2) ? 0 : s + 1;
        sp = (sp == 2) ? 0 : sp + 1;
    }

    #pragma unroll
    for (int mt = 0; mt < MT; ++mt) {
        #pragma unroll
        for (int nt = 0; nt < 4; ++nt) {
            const int m = m0 + wm + mt*16 + g;
            const int n = n0 + wn + nt*8 + c2;
            float v0 = acc[mt][nt][0], v1 = acc[mt][nt][1];
            float v2 = acc[mt][nt][2], v3 = acc[mt][nt][3];
            if (EPI == 2) {
                const float2 r0 = *reinterpret_cast<const float2*>(resid + (size_t)m*N + n);
                const float2 r1 = *reinterpret_cast<const float2*>(resid + (size_t)(m+8)*N + n);
                v0 += r0.x; v1 += r0.y; v2 += r1.x; v3 += r1.y;
            }
            *reinterpret_cast<float2*>(C + (size_t)m*N + n)     = make_float2(v0, v1);
            *reinterpret_cast<float2*>(C + (size_t)(m+8)*N + n) = make_float2(v2, v3);
        }
    }
}

#define SMEM_H4 (3*((128*GPH) + (128*GPH)))  // 110592
#define SMEM_H2 (3*(( 64*GPH) + (128*GPH)))  // 82944

// ---------------- tf32 GEMM (dt_proj only: A=f32 dbl, K=64) -------------------
#define GP 36
#define TILE_ROW_BYTES (GP*4)

template<int MT, int EPI>
__global__ __launch_bounds__(256, 2) void mma_gemm(
    const float* __restrict__ A, int lda,
    const float* __restrict__ Bw,
    float* __restrict__ C,
    int N, int K,
    const float* __restrict__ bias)
{
    constexpr int BM  = 32*MT;
    constexpr int SAB = BM * TILE_ROW_BYTES;
    constexpr int SBB = 128 * TILE_ROW_BYTES;
    constexpr int STG = SAB + SBB;

    extern __shared__ char dynsmem[];
    const uint32_t sm32 = smem_u32(dynsmem);

    const int tid  = threadIdx.x;
    const int wid  = tid >> 5, lane = tid & 31;
    const int g    = lane >> 2;
    const int c2   = (lane & 3) * 2;
    const int wm   = (wid >> 2) * (16*MT);
    const int wn   = (wid & 3) * 32;
    const int m0   = blockIdx.y * BM;
    const int n0   = blockIdx.x * 128;

    const int lrow = tid >> 3;
    const int lk16 = (tid & 7) * 16;

    const float* Ap0 = A  + (size_t)(m0 + lrow) * lda + (lk16 >> 2);
    const float* Bp0 = Bw + (size_t)(n0 + lrow) * K   + (lk16 >> 2);

    const uint32_t aoff = ((wm + (lane & 15))*GP + (lane >> 4)*4) * 4;
    const uint32_t boff = ((wn + 8*(lane >> 4) + (lane & 7))*GP + ((lane >> 3) & 1)*4) * 4;

    float acc[MT][4][4];
    #pragma unroll
    for (int i = 0; i < MT; ++i)
        #pragma unroll
        for (int j = 0; j < 4; ++j)
            #pragma unroll
            for (int q = 0; q < 4; ++q) acc[i][j][q] = 0.f;

    const int KT = K / 32;

    #pragma unroll
    for (int p = 0; p < 2; ++p) {
        if (p < KT) {
            const uint32_t da = sm32 + p*STG;
            const float* Apn = Ap0 + p*32;
            const float* Bpn = Bp0 + p*32;
            #pragma unroll
            for (int i = 0; i < MT; ++i)
                asm volatile("cp.async.cg.shared.global [%0], [%1], 16;"
                    :: "r"(da + (lrow + 32*i)*TILE_ROW_BYTES + lk16),
                       "l"(Apn + (size_t)(32*i)*lda));
            #pragma unroll
            for (int i = 0; i < 4; ++i)
                asm volatile("cp.async.cg.shared.global [%0], [%1], 16;"
                    :: "r"(da + SAB + (lrow + 32*i)*TILE_ROW_BYTES + lk16),
                       "l"(Bpn + (size_t)(32*i)*K));
            asm volatile("cp.async.commit_group;" ::: "memory");
        }
    }

    int s = 0, sp = 2;
    for (int kt = 0; kt < KT; ++kt) {
        if (kt + 1 < KT) asm volatile("cp.async.wait_group 1;" ::: "memory");
        else             asm volatile("cp.async.wait_group 0;" ::: "memory");
        __syncthreads();

        if (kt + 2 < KT) {
            const uint32_t da = sm32 + sp*STG;
            const float* Apn = Ap0 + (kt + 2)*32;
            const float* Bpn = Bp0 + (kt + 2)*32;
            #pragma unroll
            for (int i = 0; i < MT; ++i)
                asm volatile("cp.async.cg.shared.global [%0], [%1], 16;"
                    :: "r"(da + (lrow + 32*i)*TILE_ROW_BYTES + lk16),
                       "l"(Apn + (size_t)(32*i)*lda));
            #pragma unroll
            for (int i = 0; i < 4; ++i)
                asm volatile("cp.async.cg.shared.global [%0], [%1], 16;"
                    :: "r"(da + SAB + (lrow + 32*i)*TILE_ROW_BYTES + lk16),
                       "l"(Bpn + (size_t)(32*i)*K));
            asm volatile("cp.async.commit_group;" ::: "memory");
        }

        const uint32_t sA = sm32 + s*STG;
        const uint32_t sB = sA + SAB;
        #pragma unroll
        for (int k8 = 0; k8 < 4; ++k8) {
            const uint32_t kbyte = k8 * 32;
            uint32_t afr[MT][4];
            #pragma unroll
            for (int mt = 0; mt < MT; ++mt)
                ldsm4(afr[mt], sA + aoff + mt*(16*TILE_ROW_BYTES) + kbyte);
            uint32_t bfr[4][2];
            {
                uint32_t t0[4], t1[4];
                ldsm4(t0, sB + boff + kbyte);
                ldsm4(t1, sB + boff + 16*TILE_ROW_BYTES + kbyte);
                bfr[0][0]=t0[0]; bfr[0][1]=t0[1]; bfr[1][0]=t0[2]; bfr[1][1]=t0[3];
                bfr[2][0]=t1[0]; bfr[2][1]=t1[1]; bfr[3][0]=t1[2]; bfr[3][1]=t1[3];
            }
            #pragma unroll
            for (int mt = 0; mt < MT; ++mt)
                #pragma unroll
                for (int nt = 0; nt < 4; ++nt)
                    mma_tf32(acc[mt][nt], afr[mt], bfr[nt]);
        }

        s  = (s  == 2) ? 0 : s + 1;
        sp = (sp == 2) ? 0 : sp + 1;
    }

    #pragma unroll
    for (int mt = 0; mt < MT; ++mt) {
        #pragma unroll
        for (int nt = 0; nt < 4; ++nt) {
            const int m = m0 + wm + mt*16 + g;
            const int n = n0 + wn + nt*8 + c2;
            float v0 = acc[mt][nt][0], v1 = acc[mt][nt][1];
            float v2 = acc[mt][nt][2], v3 = acc[mt][nt][3];
            if (EPI == 1) {
                float b0 = bias[n], b1 = bias[n+1];
                float t0 = v0 + b0; v0 = (t0 > 20.f) ? t0 : __logf(1.f + __expf(t0));
                float t1 = v1 + b1; v1 = (t1 > 20.f) ? t1 : __logf(1.f + __expf(t1));
                float t2 = v2 + b0; v2 = (t2 > 20.f) ? t2 : __logf(1.f + __expf(t2));
                float t3 = v3 + b1; v3 = (t3 > 20.f) ? t3 : __logf(1.f + __expf(t3));
            }
            *reinterpret_cast<float2*>(C + (size_t)m*N + n)     = make_float2(v0, v1);
            *reinterpret_cast<float2*>(C + (size_t)(m+8)*N + n) = make_float2(v2, v3);
        }
    }
}

#define SMEM_MT4 (3*((128*TILE_ROW_BYTES) + (128*TILE_ROW_BYTES)))  // 110592

// ---------------- RMSNorm -> f16 ----------------
__global__ __launch_bounds__(256) void rmsnorm_kernel(
    const float* __restrict__ x, const float* __restrict__ w, __half* __restrict__ xn_h)
{
    __shared__ float red[8];
    __shared__ float s_scale;
    int m = blockIdx.x, tid = threadIdx.x;
    float4 v = reinterpret_cast<const float4*>(x + (size_t)m*DMODEL)[tid];
    float s = v.x*v.x + v.y*v.y + v.z*v.z + v.w*v.w;
    #pragma unroll
    for (int o = 16; o > 0; o >>= 1) s += __shfl_xor_sync(0xffffffffu, s, o);
    if ((tid & 31) == 0) red[tid >> 5] = s;
    __syncthreads();
    if (tid < 32) {
        float t = (tid < 8) ? red[tid] : 0.f;
        #pragma unroll
        for (int o = 4; o > 0; o >>= 1) t += __shfl_xor_sync(0xffffffffu, t, o);
        if (tid == 0) s_scale = rsqrtf(t * (1.0f/DMODEL) + 1e-6f);
    }
    __syncthreads();
    float sc = s_scale;
    float4 wv = reinterpret_cast<const float4*>(w)[tid];
    __half2* po = reinterpret_cast<__half2*>(xn_h + (size_t)m*DMODEL) + tid*2;
    po[0] = __floats2half2_rn(v.x*sc*wv.x, v.y*sc*wv.y);
    po[1] = __floats2half2_rn(v.z*sc*wv.z, v.w*sc*wv.w);
}

// ---------------- Depthwise causal conv + bias + SiLU -> f16 ----------------
__global__ __launch_bounds__(256) void conv_silu_kernel(
    const float* __restrict__ xz, const float* __restrict__ cw,
    const float* __restrict__ cb, __half* __restrict__ uc_h)
{
    int idx = blockIdx.x * 256 + threadIdx.x;
    int d = idx & (DINNER-1);
    int m = idx >> 11;
    int l = m & (LL-1);
    float4 wv = reinterpret_cast<const float4*>(cw)[d];
    const float* up = xz + (size_t)m * (2*DINNER) + d;
    float acc = cb[d];
    acc = fmaf(up[0], wv.w, acc);
    if (l >= 1) acc = fmaf(up[-1*(2*DINNER)], wv.z, acc);
    if (l >= 2) acc = fmaf(up[-2*(2*DINNER)], wv.y, acc);
    if (l >= 3) acc = fmaf(up[-3*(2*DINNER)], wv.x, acc);
    uc_h[idx] = __float2half(acc / (1.f + __expf(-acc)));
}

// ---------------- Selective scan (8 lanes/channel, 4 states/lane) ------------
#define SCH 64
__global__ __launch_bounds__(256) void scan_kernel(
    const float* __restrict__ xz,  const __half* __restrict__ uc_h,
    const float* __restrict__ dbl, const float* __restrict__ dt,
    const float* __restrict__ A_log, const float* __restrict__ D_param,
    __half* __restrict__ y_h)
{
    __shared__ float sB [SCH][DSTATE];
    __shared__ float sC [SCH][DSTATE];
    __shared__ float sdt[SCH][32];
    __shared__ float su [SCH][32];
    __shared__ float sy [SCH][32];

    const int b    = blockIdx.y;
    const int d0   = blockIdx.x * 32;
    const int tid  = threadIdx.x;
    const int w    = tid >> 5;
    const int lane = tid & 31;
    const int grp  = lane >> 3;
    const int gl   = lane & 7;
    const int c    = w*4 + grp;
    const int d    = d0 + c;
    const int n0   = gl*4;
    const int mb   = b * LL;

    float k0, k1, k2, k3;
    {
        const float4 al = *reinterpret_cast<const float4*>(A_log + d*DSTATE + n0);
        const float l2e = 1.44269504f;
        k0 = -__expf(al.x) * l2e; k1 = -__expf(al.y) * l2e;
        k2 = -__expf(al.z) * l2e; k3 = -__expf(al.w) * l2e;
    }
    const float Dd = D_param[d];
    float h0 = 0.f, h1 = 0.f, h2 = 0.f, h3 = 0.f;

    for (int c0 = 0; c0 < LL; c0 += SCH) {
        for (int idx = tid; idx < SCH*DSTATE; idx += 256) {
            int t = idx >> 5, n = idx & 31;
            int m = mb + c0 + t;
            sB[t][n] = dbl[(size_t)m*XPROJ_N + DTRANK + n];
            sC[t][n] = dbl[(size_t)m*XPROJ_N + DTRANK + DSTATE + n];
        }
        for (int idx = tid; idx < SCH*32; idx += 256) {
            int t = idx >> 5, cc = idx & 31;
            int m = mb + c0 + t;
            sdt[t][cc] = dt[(size_t)m*DINNER + d0 + cc];
            su [t][cc] = __half2float(uc_h[(size_t)m*DINNER + d0 + cc]);
        }
        __syncthreads();

        #pragma unroll 2
        for (int t = 0; t < SCH; ++t) {
            const float dtv = sdt[t][c];
            const float uv  = su[t][c];
            const float dtu = dtv * uv;
            const float4 B4 = *reinterpret_cast<const float4*>(&sB[t][n0]);
            const float4 C4 = *reinterpret_cast<const float4*>(&sC[t][n0]);
            const float a0 = ex2f(dtv * k0);
            const float a1 = ex2f(dtv * k1);
            const float a2 = ex2f(dtv * k2);
            const float a3 = ex2f(dtv * k3);
            h0 = fmaf(a0, h0, dtu * B4.x);
            h1 = fmaf(a1, h1, dtu * B4.y);
            h2 = fmaf(a2, h2, dtu * B4.z);
            h3 = fmaf(a3, h3, dtu * B4.w);
            float p = h0 * C4.x;
            p = fmaf(h1, C4.y, p);
            p = fmaf(h2, C4.z, p);
            p = fmaf(h3, C4.w, p);
            p += __shfl_xor_sync(0xffffffffu, p, 4);
            p += __shfl_xor_sync(0xffffffffu, p, 2);
            p += __shfl_xor_sync(0xffffffffu, p, 1);
            if (gl == 0) sy[t][c] = fmaf(uv, Dd, p);
        }
        __syncthreads();

        for (int idx = tid; idx < SCH*32; idx += 256) {
            int t = idx >> 5, cc = idx & 31;
            int m = mb + c0 + t;
            float zv = xz[(size_t)m*(2*DINNER) + DINNER + d0 + cc];
            float yv = sy[t][cc];
            y_h[(size_t)m*DINNER + d0 + cc] = __float2half(yv * (zv / (1.f + __expf(-zv))));
        }
    }
}

// ---------------- Launch ----------------
extern "C" void kernel_launch(void* const* d_in, const int* in_sizes, int n_in,
                              void* d_out, int out_size)
{
    const float* x         = (const float*)d_in[0];
    const float* norm_w    = (const float*)d_in[1];
    const float* in_proj_w = (const float*)d_in[2];
    const float* conv_w    = (const float*)d_in[3];
    const float* conv_b    = (const float*)d_in[4];
    const float* x_proj_w  = (const float*)d_in[5];
    const float* dt_proj_w = (const float*)d_in[6];
    const float* dt_proj_b = (const float*)d_in[7];
    const float* A_log     = (const float*)d_in[8];
    const float* D_param   = (const float*)d_in[9];
    const float* out_proj_w= (const float*)d_in[10];
    float* out = (float*)d_out;

    float *p_xz, *p_dbl, *p_dt;
    __half *p_xn_h, *p_uc_h, *p_y_h, *p_wip_h, *p_wxp_h, *p_wop_h;
    cudaGetSymbolAddress((void**)&p_xz,   g_xz);
    cudaGetSymbolAddress((void**)&p_dbl,  g_dbl);
    cudaGetSymbolAddress((void**)&p_dt,   g_dt);
    cudaGetSymbolAddress((void**)&p_xn_h, g_xn_h);
    cudaGetSymbolAddress((void**)&p_uc_h, g_uc_h);
    cudaGetSymbolAddress((void**)&p_y_h,  g_y_h);
    cudaGetSymbolAddress((void**)&p_wip_h, g_wip_h);
    cudaGetSymbolAddress((void**)&p_wxp_h, g_wxp_h);
    cudaGetSymbolAddress((void**)&p_wop_h, g_wop_h);
    cudaFuncSetAttribute(hgemm<4,0>, cudaFuncAttributeMaxDynamicSharedMemorySize, SMEM_H4);
    cudaFuncSetAttribute(hgemm<2,0>, cudaFuncAttributeMaxDynamicSharedMemorySize, SMEM_H2);
    cudaFuncSetAttribute(hgemm<4,2>, cudaFuncAttributeMaxDynamicSharedMemorySize, SMEM_H4);
    cudaFuncSetAttribute(mma_gemm<4,1>, cudaFuncAttributeMaxDynamicSharedMemorySize, SMEM_MT4);

    // 0) weight conversions f32 -> f16
    cvt_h_kernel<<<((2*DINNER)*DMODEL/4 + 255)/256, 256>>>(in_proj_w,  p_wip_h, (2*DINNER)*DMODEL/4);
    cvt_h_kernel<<<(XPROJ_N*DINNER/4   + 255)/256, 256>>>(x_proj_w,   p_wxp_h, XPROJ_N*DINNER/4);
    cvt_h_kernel<<<(DMODEL*DINNER/4    + 255)/256, 256>>>(out_proj_w, p_wop_h, DMODEL*DINNER/4);

    // 1) RMSNorm -> f16
    rmsnorm_kernel<<<MM, 256>>>(x, norm_w, p_xn_h);

    // 2) in_proj (f16): xz = xn @ in_proj_w^T
    hgemm<4,0><<<dim3((2*DINNER)/128, MM/128), 256, SMEM_H4>>>(
        p_xn_h, DMODEL, p_wip_h, p_xz, 2*DINNER, DMODEL, nullptr);

    // 3) conv + silu -> f16
    conv_silu_kernel<<<(MM*DINNER)/256, 256>>>(p_xz, conv_w, conv_b, p_uc_h);

    // 4) x_proj (f16): dbl = uc @ x_proj_w^T
    hgemm<2,0><<<dim3(XPROJ_N/128, MM/64), 256, SMEM_H2>>>(
        p_uc_h, DINNER, p_wxp_h, p_dbl, XPROJ_N, DINNER, nullptr);

    // 5) dt_proj + softplus (tf32; A = dbl cols 0..63, lda=128)
    mma_gemm<4,1><<<dim3(DINNER/128, MM/128), 256, SMEM_MT4>>>(
        p_dbl, XPROJ_N, dt_proj_w, p_dt, DINNER, DTRANK, dt_proj_b);

    // 6) selective scan + skip + gate -> y f16
    scan_kernel<<<dim3(DINNER/32, BB), 256>>>(
        p_xz, p_uc_h, p_dbl, p_dt, A_log, D_param, p_y_h);

    // 7) out_proj (f16) + residual
    hgemm<4,2><<<dim3(DMODEL/128, MM/128), 256, SMEM_H4>>>(
        p_y_h, DINNER, p_wop_h, out, DMODEL, DINNER, x);
}

// round 16
// speedup vs baseline: 1.9185x; 1.0020x over previous
#include <cuda_runtime.h>
#include <cuda_bf16.h>
#include <cuda_fp16.h>
#include <math.h>
#include <stdint.h>

// ---------------- Problem constants ----------------
#define BB 4
#define LL 2048
#define DMODEL 1024
#define DINNER 2048
#define DSTATE 32
#define DTRANK 64
#define MM (BB*LL)          // 8192 rows
#define XPROJ_N 128

// ---------------- Scratch ----------------
__device__ float  g_xz [MM*(2*DINNER)];
__device__ float  g_dbl[MM*XPROJ_N];
__device__ float  g_dt [MM*DINNER];
__device__ __half g_xn_h [MM*DMODEL];
__device__ __half g_uc_h [MM*DINNER];
__device__ __half g_y_h  [MM*DINNER];
__device__ __half g_wip_h[(2*DINNER)*DMODEL];
__device__ __half g_wxp_h[XPROJ_N*DINNER];
__device__ __half g_wop_h[DMODEL*DINNER];

// ---------------- helpers ----------------
__device__ __forceinline__ uint32_t smem_u32(const void* p){
    uint32_t a;
    asm("{ .reg .u64 t; cvta.to.shared.u64 t, %1; cvt.u32.u64 %0, t; }" : "=r"(a) : "l"(p));
    return a;
}
__device__ __forceinline__ float ex2f(float x){
    float r; asm("ex2.approx.f32 %0, %1;" : "=f"(r) : "f"(x)); return r;
}
__device__ __forceinline__ void mma_tf32(float* c, const uint32_t* a, const uint32_t* b){
    asm volatile(
        "mma.sync.aligned.m16n8k8.row.col.f32.tf32.tf32.f32 "
        "{%0,%1,%2,%3}, {%4,%5,%6,%7}, {%8,%9}, {%0,%1,%2,%3};"
        : "+f"(c[0]), "+f"(c[1]), "+f"(c[2]), "+f"(c[3])
        : "r"(a[0]), "r"(a[1]), "r"(a[2]), "r"(a[3]), "r"(b[0]), "r"(b[1]));
}
__device__ __forceinline__ void mma_f16(float* c, const uint32_t* a, const uint32_t* b){
    asm volatile(
        "mma.sync.aligned.m16n8k16.row.col.f32.f16.f16.f32 "
        "{%0,%1,%2,%3}, {%4,%5,%6,%7}, {%8,%9}, {%0,%1,%2,%3};"
        : "+f"(c[0]), "+f"(c[1]), "+f"(c[2]), "+f"(c[3])
        : "r"(a[0]), "r"(a[1]), "r"(a[2]), "r"(a[3]), "r"(b[0]), "r"(b[1]));
}
__device__ __forceinline__ void ldsm4(uint32_t* r, uint32_t addr){
    asm volatile("ldmatrix.sync.aligned.m8n8.x4.shared.b16 {%0,%1,%2,%3}, [%4];"
        : "=r"(r[0]), "=r"(r[1]), "=r"(r[2]), "=r"(r[3]) : "r"(addr));
}

// ---------------- f32 -> f16 convert (weights) ----------------
__global__ __launch_bounds__(256) void cvt_h_kernel(
    const float* __restrict__ src, __half* __restrict__ dst, int n4)
{
    int i = blockIdx.x * 256 + threadIdx.x;
    if (i < n4) {
        float4 v = reinterpret_cast<const float4*>(src)[i];
        __half2* po = reinterpret_cast<__half2*>(dst) + i*2;
        po[0] = __floats2half2_rn(v.x, v.y);
        po[1] = __floats2half2_rn(v.z, v.w);
    }
}

// ---------------- fp16 mma.sync GEMM (3-stage, 1 barrier/ktile) ---------------
// C[m,n] = sum_k A[m,k]*Bw[n,k]; A,Bw f16 row-major, C f32.
// BM=32*MT, BN=128, BK=64 halves (128B rows, pitch 144B). 256 thr, 8 warps 2x4.
// EPI: 0 none, 2 acc+resid.
#define GPH 144   // f16 row pitch bytes

template<int MT, int EPI>
__global__ __launch_bounds__(256, 2) void hgemm(
    const __half* __restrict__ A, int lda,
    const __half* __restrict__ Bw,
    float* __restrict__ C,
    int N, int K,
    const float* __restrict__ resid)
{
    constexpr int BM  = 32*MT;
    constexpr int SAB = BM * GPH;
    constexpr int SBB = 128 * GPH;
    constexpr int STG = SAB + SBB;

    extern __shared__ char dynsmem[];
    const uint32_t sm32 = smem_u32(dynsmem);

    const int tid  = threadIdx.x;
    const int wid  = tid >> 5, lane = tid & 31;
    const int g    = lane >> 2;
    const int c2   = (lane & 3) * 2;
    const int wm   = (wid >> 2) * (16*MT);
    const int wn   = (wid & 3) * 32;
    const int m0   = blockIdx.y * BM;
    const int n0   = blockIdx.x * 128;

    const int lrow = tid >> 3;           // 0..31
    const int lh16 = (tid & 7) * 8;      // half offset (16B chunk)

    const __half* Ap0 = A  + (size_t)(m0 + lrow) * lda + lh16;
    const __half* Bp0 = Bw + (size_t)(n0 + lrow) * K   + lh16;

    // ldmatrix base byte offsets (within a stage)
    const uint32_t aoffB = (uint32_t)(wm + (lane & 15))*GPH + (lane >> 4)*16;
    const uint32_t boffB = (uint32_t)(wn + 8*(lane >> 4) + (lane & 7))*GPH + ((lane >> 3) & 1)*16;

    float acc[MT][4][4];
    #pragma unroll
    for (int i = 0; i < MT; ++i)
        #pragma unroll
        for (int j = 0; j < 4; ++j)
            #pragma unroll
            for (int q = 0; q < 4; ++q) acc[i][j][q] = 0.f;

    const int KT = K / 64;

    // prologue: tiles 0,1 -> stages 0,1
    #pragma unroll
    for (int p = 0; p < 2; ++p) {
        if (p < KT) {
            const uint32_t da = sm32 + p*STG;
            const __half* Apn = Ap0 + p*64;
            const __half* Bpn = Bp0 + p*64;
            #pragma unroll
            for (int i = 0; i < MT; ++i)
                asm volatile("cp.async.cg.shared.global [%0], [%1], 16;"
                    :: "r"(da + (lrow + 32*i)*GPH + (tid & 7)*16),
                       "l"(Apn + (size_t)(32*i)*lda));
            #pragma unroll
            for (int i = 0; i < 4; ++i)
                asm volatile("cp.async.cg.shared.global [%0], [%1], 16;"
                    :: "r"(da + SAB + (lrow + 32*i)*GPH + (tid & 7)*16),
                       "l"(Bpn + (size_t)(32*i)*K));
            asm volatile("cp.async.commit_group;" ::: "memory");
        }
    }

    int s = 0, sp = 2;
    for (int kt = 0; kt < KT; ++kt) {
        if (kt + 1 < KT) asm volatile("cp.async.wait_group 1;" ::: "memory");
        else             asm volatile("cp.async.wait_group 0;" ::: "memory");
        __syncthreads();

        if (kt + 2 < KT) {
            const uint32_t da = sm32 + sp*STG;
            const __half* Apn = Ap0 + (kt + 2)*64;
            const __half* Bpn = Bp0 + (kt + 2)*64;
            #pragma unroll
            for (int i = 0; i < MT; ++i)
                asm volatile("cp.async.cg.shared.global [%0], [%1], 16;"
                    :: "r"(da + (lrow + 32*i)*GPH + (tid & 7)*16),
                       "l"(Apn + (size_t)(32*i)*lda));
            #pragma unroll
            for (int i = 0; i < 4; ++i)
                asm volatile("cp.async.cg.shared.global [%0], [%1], 16;"
                    :: "r"(da + SAB + (lrow + 32*i)*GPH + (tid & 7)*16),
                       "l"(Bpn + (size_t)(32*i)*K));
            asm volatile("cp.async.commit_group;" ::: "memory");
        }

        const uint32_t sA = sm32 + s*STG;
        const uint32_t sB = sA + SAB;
        #pragma unroll
        for (int k16 = 0; k16 < 4; ++k16) {
            const uint32_t kbyte = k16 * 32;   // 16 halves
            uint32_t afr[MT][4];
            #pragma unroll
            for (int mt = 0; mt < MT; ++mt)
                ldsm4(afr[mt], sA + aoffB + mt*(16*GPH) + kbyte);
            uint32_t bfr[4][2];
            {
                uint32_t t0[4], t1[4];
                ldsm4(t0, sB + boffB + kbyte);              // nt0, nt1
                ldsm4(t1, sB + boffB + 16*GPH + kbyte);     // nt2, nt3
                bfr[0][0]=t0[0]; bfr[0][1]=t0[1]; bfr[1][0]=t0[2]; bfr[1][1]=t0[3];
                bfr[2][0]=t1[0]; bfr[2][1]=t1[1]; bfr[3][0]=t1[2]; bfr[3][1]=t1[3];
            }
            #pragma unroll
            for (int mt = 0; mt < MT; ++mt)
                #pragma unroll
                for (int nt = 0; nt < 4; ++nt)
                    mma_f16(acc[mt][nt], afr[mt], bfr[nt]);
        }

        s  = (s  == 2) ? 0 : s + 1;
        sp = (sp == 2) ? 0 : sp + 1;
    }

    #pragma unroll
    for (int mt = 0; mt < MT; ++mt) {
        #pragma unroll
        for (int nt = 0; nt < 4; ++nt) {
            const int m = m0 + wm + mt*16 + g;
            const int n = n0 + wn + nt*8 + c2;
            float v0 = acc[mt][nt][0], v1 = acc[mt][nt][1];
            float v2 = acc[mt][nt][2], v3 = acc[mt][nt][3];
            if (EPI == 2) {
                const float2 r0 = *reinterpret_cast<const float2*>(resid + (size_t)m*N + n);
                const float2 r1 = *reinterpret_cast<const float2*>(resid + (size_t)(m+8)*N + n);
                v0 += r0.x; v1 += r0.y; v2 += r1.x; v3 += r1.y;
            }
            *reinterpret_cast<float2*>(C + (size_t)m*N + n)     = make_float2(v0, v1);
            *reinterpret_cast<float2*>(C + (size_t)(m+8)*N + n) = make_float2(v2, v3);
        }
    }
}

#define SMEM_H4 (3*((128*GPH) + (128*GPH)))  // 110592
#define SMEM_H2 (3*(( 64*GPH) + (128*GPH)))  // 82944

// ---------------- tf32 GEMM (dt_proj only: A=f32 dbl, K=64) -------------------
#define GP 36
#define TILE_ROW_BYTES (GP*4)

template<int MT, int EPI>
__global__ __launch_bounds__(256, 2) void mma_gemm(
    const float* __restrict__ A, int lda,
    const float* __restrict__ Bw,
    float* __restrict__ C,
    int N, int K,
    const float* __restrict__ bias)
{
    constexpr int BM  = 32*MT;
    constexpr int SAB = BM * TILE_ROW_BYTES;
    constexpr int SBB = 128 * TILE_ROW_BYTES;
    constexpr int STG = SAB + SBB;

    extern __shared__ char dynsmem[];
    const uint32_t sm32 = smem_u32(dynsmem);

    const int tid  = threadIdx.x;
    const int wid  = tid >> 5, lane = tid & 31;
    const int g    = lane >> 2;
    const int c2   = (lane & 3) * 2;
    const int wm   = (wid >> 2) * (16*MT);
    const int wn   = (wid & 3) * 32;
    const int m0   = blockIdx.y * BM;
    const int n0   = blockIdx.x * 128;

    const int lrow = tid >> 3;
    const int lk16 = (tid & 7) * 16;

    const float* Ap0 = A  + (size_t)(m0 + lrow) * lda + (lk16 >> 2);
    const float* Bp0 = Bw + (size_t)(n0 + lrow) * K   + (lk16 >> 2);

    const uint32_t aoff = ((wm + (lane & 15))*GP + (lane >> 4)*4) * 4;
    const uint32_t boff = ((wn + 8*(lane >> 4) + (lane & 7))*GP + ((lane >> 3) & 1)*4) * 4;

    float acc[MT][4][4];
    #pragma unroll
    for (int i = 0; i < MT; ++i)
        #pragma unroll
        for (int j = 0; j < 4; ++j)
            #pragma unroll
            for (int q = 0; q < 4; ++q) acc[i][j][q] = 0.f;

    const int KT = K / 32;

    #pragma unroll
    for (int p = 0; p < 2; ++p) {
        if (p < KT) {
            const uint32_t da = sm32 + p*STG;
            const float* Apn = Ap0 + p*32;
            const float* Bpn = Bp0 + p*32;
            #pragma unroll
            for (int i = 0; i < MT; ++i)
                asm volatile("cp.async.cg.shared.global [%0], [%1], 16;"
                    :: "r"(da + (lrow + 32*i)*TILE_ROW_BYTES + lk16),
                       "l"(Apn + (size_t)(32*i)*lda));
            #pragma unroll
            for (int i = 0; i < 4; ++i)
                asm volatile("cp.async.cg.shared.global [%0], [%1], 16;"
                    :: "r"(da + SAB + (lrow + 32*i)*TILE_ROW_BYTES + lk16),
                       "l"(Bpn + (size_t)(32*i)*K));
            asm volatile("cp.async.commit_group;" ::: "memory");
        }
    }

    int s = 0, sp = 2;
    for (int kt = 0; kt < KT; ++kt) {
        if (kt + 1 < KT) asm volatile("cp.async.wait_group 1;" ::: "memory");
        else             asm volatile("cp.async.wait_group 0;" ::: "memory");
        __syncthreads();

        if (kt + 2 < KT) {
            const uint32_t da = sm32 + sp*STG;
            const float* Apn = Ap0 + (kt + 2)*32;
            const float* Bpn = Bp0 + (kt + 2)*32;
            #pragma unroll
            for (int i = 0; i < MT; ++i)
                asm volatile("cp.async.cg.shared.global [%0], [%1], 16;"
                    :: "r"(da + (lrow + 32*i)*TILE_ROW_BYTES + lk16),
                       "l"(Apn + (size_t)(32*i)*lda));
            #pragma unroll
            for (int i = 0; i < 4; ++i)
                asm volatile("cp.async.cg.shared.global [%0], [%1], 16;"
                    :: "r"(da + SAB + (lrow + 32*i)*TILE_ROW_BYTES + lk16),
                       "l"(Bpn + (size_t)(32*i)*K));
            asm volatile("cp.async.commit_group;" ::: "memory");
        }

        const uint32_t sA = sm32 + s*STG;
        const uint32_t sB = sA + SAB;
        #pragma unroll
        for (int k8 = 0; k8 < 4; ++k8) {
            const uint32_t kbyte = k8 * 32;
            uint32_t afr[MT][4];
            #pragma unroll
            for (int mt = 0; mt < MT; ++mt)
                ldsm4(afr[mt], sA + aoff + mt*(16*TILE_ROW_BYTES) + kbyte);
            uint32_t bfr[4][2];
            {
                uint32_t t0[4], t1[4];
                ldsm4(t0, sB + boff + kbyte);
                ldsm4(t1, sB + boff + 16*TILE_ROW_BYTES + kbyte);
                bfr[0][0]=t0[0]; bfr[0][1]=t0[1]; bfr[1][0]=t0[2]; bfr[1][1]=t0[3];
                bfr[2][0]=t1[0]; bfr[2][1]=t1[1]; bfr[3][0]=t1[2]; bfr[3][1]=t1[3];
            }
            #pragma unroll
            for (int mt = 0; mt < MT; ++mt)
                #pragma unroll
                for (int nt = 0; nt < 4; ++nt)
                    mma_tf32(acc[mt][nt], afr[mt], bfr[nt]);
        }

        s  = (s  == 2) ? 0 : s + 1;
        sp = (sp == 2) ? 0 : sp + 1;
    }

    #pragma unroll
    for (int mt = 0; mt < MT; ++mt) {
        #pragma unroll
        for (int nt = 0; nt < 4; ++nt) {
            const int m = m0 + wm + mt*16 + g;
            const int n = n0 + wn + nt*8 + c2;
            float v0 = acc[mt][nt][0], v1 = acc[mt][nt][1];
            float v2 = acc[mt][nt][2], v3 = acc[mt][nt][3];
            if (EPI == 1) {
                float b0 = bias[n], b1 = bias[n+1];
                float t0 = v0 + b0; v0 = (t0 > 20.f) ? t0 : __logf(1.f + __expf(t0));
                float t1 = v1 + b1; v1 = (t1 > 20.f) ? t1 : __logf(1.f + __expf(t1));
                float t2 = v2 + b0; v2 = (t2 > 20.f) ? t2 : __logf(1.f + __expf(t2));
                float t3 = v3 + b1; v3 = (t3 > 20.f) ? t3 : __logf(1.f + __expf(t3));
            }
            *reinterpret_cast<float2*>(C + (size_t)m*N + n)     = make_float2(v0, v1);
            *reinterpret_cast<float2*>(C + (size_t)(m+8)*N + n) = make_float2(v2, v3);
        }
    }
}

#define SMEM_MT4 (3*((128*TILE_ROW_BYTES) + (128*TILE_ROW_BYTES)))  // 110592

// ---------------- RMSNorm -> f16 ----------------
__global__ __launch_bounds__(256) void rmsnorm_kernel(
    const float* __restrict__ x, const float* __restrict__ w, __half* __restrict__ xn_h)
{
    __shared__ float red[8];
    __shared__ float s_scale;
    int m = blockIdx.x, tid = threadIdx.x;
    float4 v = reinterpret_cast<const float4*>(x + (size_t)m*DMODEL)[tid];
    float s = v.x*v.x + v.y*v.y + v.z*v.z + v.w*v.w;
    #pragma unroll
    for (int o = 16; o > 0; o >>= 1) s += __shfl_xor_sync(0xffffffffu, s, o);
    if ((tid & 31) == 0) red[tid >> 5] = s;
    __syncthreads();
    if (tid < 32) {
        float t = (tid < 8) ? red[tid] : 0.f;
        #pragma unroll
        for (int o = 4; o > 0; o >>= 1) t += __shfl_xor_sync(0xffffffffu, t, o);
        if (tid == 0) s_scale = rsqrtf(t * (1.0f/DMODEL) + 1e-6f);
    }
    __syncthreads();
    float sc = s_scale;
    float4 wv = reinterpret_cast<const float4*>(w)[tid];
    __half2* po = reinterpret_cast<__half2*>(xn_h + (size_t)m*DMODEL) + tid*2;
    po[0] = __floats2half2_rn(v.x*sc*wv.x, v.y*sc*wv.y);
    po[1] = __floats2half2_rn(v.z*sc*wv.z, v.w*sc*wv.w);
}

// ---------------- Depthwise causal conv + bias + SiLU -> f16 ----------------
__global__ __launch_bounds__(256) void conv_silu_kernel(
    const float* __restrict__ xz, const float* __restrict__ cw,
    const float* __restrict__ cb, __half* __restrict__ uc_h)
{
    int idx = blockIdx.x * 256 + threadIdx.x;
    int d = idx & (DINNER-1);
    int m = idx >> 11;
    int l = m & (LL-1);
    float4 wv = reinterpret_cast<const float4*>(cw)[d];
    const float* up = xz + (size_t)m * (2*DINNER) + d;
    float acc = cb[d];
    acc = fmaf(up[0], wv.w, acc);
    if (l >= 1) acc = fmaf(up[-1*(2*DINNER)], wv.z, acc);
    if (l >= 2) acc = fmaf(up[-2*(2*DINNER)], wv.y, acc);
    if (l >= 3) acc = fmaf(up[-3*(2*DINNER)], wv.x, acc);
    uc_h[idx] = __float2half(acc / (1.f + __expf(-acc)));
}

// ---------------- Selective scan (8 lanes/channel, 4 states/lane) ------------
#define SCH 64
__global__ __launch_bounds__(256) void scan_kernel(
    const float* __restrict__ xz,  const __half* __restrict__ uc_h,
    const float* __restrict__ dbl, const float* __restrict__ dt,
    const float* __restrict__ A_log, const float* __restrict__ D_param,
    __half* __restrict__ y_h)
{
    __shared__ float sB [SCH][DSTATE];
    __shared__ float sC [SCH][DSTATE];
    __shared__ float sdt[SCH][32];
    __shared__ float su [SCH][32];
    __shared__ float sy [SCH][32];

    const int b    = blockIdx.y;
    const int d0   = blockIdx.x * 32;
    const int tid  = threadIdx.x;
    const int w    = tid >> 5;
    const int lane = tid & 31;
    const int grp  = lane >> 3;
    const int gl   = lane & 7;
    const int c    = w*4 + grp;
    const int d    = d0 + c;
    const int n0   = gl*4;
    const int mb   = b * LL;

    float k0, k1, k2, k3;
    {
        const float4 al = *reinterpret_cast<const float4*>(A_log + d*DSTATE + n0);
        const float l2e = 1.44269504f;
        k0 = -__expf(al.x) * l2e; k1 = -__expf(al.y) * l2e;
        k2 = -__expf(al.z) * l2e; k3 = -__expf(al.w) * l2e;
    }
    const float Dd = D_param[d];
    float h0 = 0.f, h1 = 0.f, h2 = 0.f, h3 = 0.f;

    for (int c0 = 0; c0 < LL; c0 += SCH) {
        for (int idx = tid; idx < SCH*DSTATE; idx += 256) {
            int t = idx >> 5, n = idx & 31;
            int m = mb + c0 + t;
            sB[t][n] = dbl[(size_t)m*XPROJ_N + DTRANK + n];
            sC[t][n] = dbl[(size_t)m*XPROJ_N + DTRANK + DSTATE + n];
        }
        for (int idx = tid; idx < SCH*32; idx += 256) {
            int t = idx >> 5, cc = idx & 31;
            int m = mb + c0 + t;
            sdt[t][cc] = dt[(size_t)m*DINNER + d0 + cc];
            su [t][cc] = __half2float(uc_h[(size_t)m*DINNER + d0 + cc]);
        }
        __syncthreads();

        #pragma unroll 2
        for (int t = 0; t < SCH; ++t) {
            const float dtv = sdt[t][c];
            const float uv  = su[t][c];
            const float dtu = dtv * uv;
            const float4 B4 = *reinterpret_cast<const float4*>(&sB[t][n0]);
            const float4 C4 = *reinterpret_cast<const float4*>(&sC[t][n0]);
            const float a0 = ex2f(dtv * k0);
            const float a1 = ex2f(dtv * k1);
            const float a2 = ex2f(dtv * k2);
            const float a3 = ex2f(dtv * k3);
            h0 = fmaf(a0, h0, dtu * B4.x);
            h1 = fmaf(a1, h1, dtu * B4.y);
            h2 = fmaf(a2, h2, dtu * B4.z);
            h3 = fmaf(a3, h3, dtu * B4.w);
            float p = h0 * C4.x;
            p = fmaf(h1, C4.y, p);
            p = fmaf(h2, C4.z, p);
            p = fmaf(h3, C4.w, p);
            p += __shfl_xor_sync(0xffffffffu, p, 4);
            p += __shfl_xor_sync(0xffffffffu, p, 2);
            p += __shfl_xor_sync(0xffffffffu, p, 1);
            if (gl == 0) sy[t][c] = fmaf(uv, Dd, p);
        }
        __syncthreads();

        for (int idx = tid; idx < SCH*32; idx += 256) {
            int t = idx >> 5, cc = idx & 31;
            int m = mb + c0 + t;
            float zv = xz[(size_t)m*(2*DINNER) + DINNER + d0 + cc];
            float yv = sy[t][cc];
            y_h[(size_t)m*DINNER + d0 + cc] = __float2half(yv * (zv / (1.f + __expf(-zv))));
        }
    }
}

// ---------------- Launch ----------------
extern "C" void kernel_launch(void* const* d_in, const int* in_sizes, int n_in,
                              void* d_out, int out_size)
{
    const float* x         = (const float*)d_in[0];
    const float* norm_w    = (const float*)d_in[1];
    const float* in_proj_w = (const float*)d_in[2];
    const float* conv_w    = (const float*)d_in[3];
    const float* conv_b    = (const float*)d_in[4];
    const float* x_proj_w  = (const float*)d_in[5];
    const float* dt_proj_w = (const float*)d_in[6];
    const float* dt_proj_b = (const float*)d_in[7];
    const float* A_log     = (const float*)d_in[8];
    const float* D_param   = (const float*)d_in[9];
    const float* out_proj_w= (const float*)d_in[10];
    float* out = (float*)d_out;

    float *p_xz, *p_dbl, *p_dt;
    __half *p_xn_h, *p_uc_h, *p_y_h, *p_wip_h, *p_wxp_h, *p_wop_h;
    cudaGetSymbolAddress((void**)&p_xz,   g_xz);
    cudaGetSymbolAddress((void**)&p_dbl,  g_dbl);
    cudaGetSymbolAddress((void**)&p_dt,   g_dt);
    cudaGetSymbolAddress((void**)&p_xn_h, g_xn_h);
    cudaGetSymbolAddress((void**)&p_uc_h, g_uc_h);
    cudaGetSymbolAddress((void**)&p_y_h,  g_y_h);
    cudaGetSymbolAddress((void**)&p_wip_h, g_wip_h);
    cudaGetSymbolAddress((void**)&p_wxp_h, g_wxp_h);
    cudaGetSymbolAddress((void**)&p_wop_h, g_wop_h);
    cudaFuncSetAttribute(hgemm<4,0>, cudaFuncAttributeMaxDynamicSharedMemorySize, SMEM_H4);
    cudaFuncSetAttribute(hgemm<2,0>, cudaFuncAttributeMaxDynamicSharedMemorySize, SMEM_H2);
    cudaFuncSetAttribute(hgemm<4,2>, cudaFuncAttributeMaxDynamicSharedMemorySize, SMEM_H4);
    cudaFuncSetAttribute(mma_gemm<4,1>, cudaFuncAttributeMaxDynamicSharedMemorySize, SMEM_MT4);

    // 0) weight conversions f32 -> f16
    cvt_h_kernel<<<((2*DINNER)*DMODEL/4 + 255)/256, 256>>>(in_proj_w,  p_wip_h, (2*DINNER)*DMODEL/4);
    cvt_h_kernel<<<(XPROJ_N*DINNER/4   + 255)/256, 256>>>(x_proj_w,   p_wxp_h, XPROJ_N*DINNER/4);
    cvt_h_kernel<<<(DMODEL*DINNER/4    + 255)/256, 256>>>(out_proj_w, p_wop_h, DMODEL*DINNER/4);

    // 1) RMSNorm -> f16
    rmsnorm_kernel<<<MM, 256>>>(x, norm_w, p_xn_h);

    // 2) in_proj (f16): xz = xn @ in_proj_w^T
    hgemm<4,0><<<dim3((2*DINNER)/128, MM/128), 256, SMEM_H4>>>(
        p_xn_h, DMODEL, p_wip_h, p_xz, 2*DINNER, DMODEL, nullptr);

    // 3) conv + silu -> f16
    conv_silu_kernel<<<(MM*DINNER)/256, 256>>>(p_xz, conv_w, conv_b, p_uc_h);

    // 4) x_proj (f16): dbl = uc @ x_proj_w^T
    hgemm<2,0><<<dim3(XPROJ_N/128, MM/64), 256, SMEM_H2>>>(
        p_uc_h, DINNER, p_wxp_h, p_dbl, XPROJ_N, DINNER, nullptr);

    // 5) dt_proj + softplus (tf32; A = dbl cols 0..63, lda=128)
    mma_gemm<4,1><<<dim3(DINNER/128, MM/128), 256, SMEM_MT4>>>(
        p_dbl, XPROJ_N, dt_proj_w, p_dt, DINNER, DTRANK, dt_proj_b);

    // 6) selective scan + skip + gate -> y f16
    scan_kernel<<<dim3(DINNER/32, BB), 256>>>(
        p_xz, p_uc_h, p_dbl, p_dt, A_log, D_param, p_y_h);

    // 7) out_proj (f16) + residual
    hgemm<4,2><<<dim3(DMODEL/128, MM/128), 256, SMEM_H4>>>(
        p_y_h, DINNER, p_wop_h, out, DMODEL, DINNER, x);
}